// round 4
// baseline (speedup 1.0000x reference)
#include <cuda_runtime.h>
#include <cuda_bf16.h>

#define D    256
#define F    1024
#define NL   4
#define NC   10
#define B16  16
#define GRID 128
#define TPB  256

// ---------------- device scratch (no allocs allowed) ----------------
__device__ float g_wc[NL * D * D];   // combined wv@wo per layer (1 MB)
__device__ float g_h [B16 * D];      // residual stream (ping)
__device__ float g_h2[B16 * D];      // residual stream (pong)
__device__ float g_g [B16 * F];      // MLP hidden

// ---------------- grid barrier state ----------------
__device__ unsigned g_cnt[8];
__device__ unsigned g_root;
__device__ volatile unsigned g_sense;

__device__ __forceinline__ void grid_barrier(unsigned target) {
    __syncthreads();
    if (threadIdx.x == 0) {
        __threadfence();
        unsigned grp = blockIdx.x & 7u;
        if (atomicAdd(&g_cnt[grp], 1u) == (GRID / 8 - 1)) {
            atomicExch(&g_cnt[grp], 0u);
            __threadfence();
            if (atomicAdd(&g_root, 1u) == 7u) {
                atomicExch(&g_root, 0u);
                __threadfence();
                g_sense = target;
            }
        }
        while (g_sense != target) { }
        __threadfence();
    }
    __syncthreads();
}

// block-wide sum over 256 threads
__device__ __forceinline__ float blockReduceSum(float v, float* red) {
    #pragma unroll
    for (int o = 16; o > 0; o >>= 1) v += __shfl_xor_sync(0xffffffffu, v, o);
    int wid = threadIdx.x >> 5;
    if ((threadIdx.x & 31) == 0) red[wid] = v;
    __syncthreads();
    if (threadIdx.x < 8) {
        v = red[threadIdx.x];
        #pragma unroll
        for (int o = 4; o > 0; o >>= 1) v += __shfl_xor_sync(0xffu, v, o);
        if (threadIdx.x == 0) red[0] = v;
    }
    __syncthreads();
    float r = red[0];
    __syncthreads();
    return r;
}

__device__ __forceinline__ float gelu_tanh(float x) {
    const float c = 0.7978845608028654f;   // sqrt(2/pi)
    float u = c * (x + 0.044715f * x * x * x);
    return 0.5f * x * (1.0f + tanhf(u));
}

__global__ void __launch_bounds__(TPB)
performer_cls_kernel(const int*   __restrict__ xx,
                     const float* __restrict__ emb_tok,
                     const float* __restrict__ emb_pos,
                     const float* __restrict__ ln1_s,
                     const float* __restrict__ ln1_b,
                     const float* __restrict__ wv,
                     const float* __restrict__ wo,
                     const float* __restrict__ bo,
                     const float* __restrict__ ln2_s,
                     const float* __restrict__ ln2_b,
                     const float* __restrict__ w1,
                     const float* __restrict__ b1,
                     const float* __restrict__ w2,
                     const float* __restrict__ b2,
                     const float* __restrict__ wcls,
                     const float* __restrict__ bcls,
                     float* __restrict__ out,
                     int N)
{
    __shared__ float buf[8192];    // 32KB carved per stage
    __shared__ float red[8];
    __shared__ unsigned sh_sense;

    const int tid = threadIdx.x;
    const int blk = blockIdx.x;

    // read barrier sense base before any arrival (stable across replays)
    if (tid == 0) sh_sense = g_sense;
    __syncthreads();
    unsigned sense = sh_sense;

    // ============ stage 0: h init (blocks 0..15) + Wcomb precompute (all) ===
    if (blk < B16) {
        const int tok = xx[blk * N];
        __stcg(g_h + blk * D + tid, emb_tok[tok * D + tid] + emb_pos[tid]);
    }
    {
        // blk -> (layer, 8-row tile of Wcomb)
        const int l  = blk >> 5;
        const int i0 = (blk & 31) * 8;
        const float* wv_l = wv + (size_t)l * D * D;
        const float* wo_l = wo + (size_t)l * D * D;
        float*       wc_l = g_wc + (size_t)l * D * D;

        // sh_wv rows: buf[0..2047]
        for (int i = tid; i < 8 * D; i += TPB)
            buf[i] = wv_l[(i0 + (i >> 8)) * D + (i & 255)];

        float* sh_wo = buf + 2048;     // 16 x 256 chunk
        const int c4 = tid & 63;       // 4 cols
        const int rr = tid >> 6;       // rows rr and rr+4
        float4 a0 = make_float4(0.f,0.f,0.f,0.f);
        float4 a1 = make_float4(0.f,0.f,0.f,0.f);

        for (int k0 = 0; k0 < D; k0 += 16) {
            __syncthreads();
            for (int i = tid * 4; i < 16 * D; i += TPB * 4)
                *(float4*)(sh_wo + i) = *(const float4*)(wo_l + (k0 + (i >> 8)) * D + (i & 255));
            __syncthreads();
            #pragma unroll
            for (int kk = 0; kk < 16; ++kk) {
                float4 w = *(float4*)(sh_wo + kk * D + c4 * 4);
                float va = buf[rr * D + k0 + kk];
                float vb = buf[(rr + 4) * D + k0 + kk];
                a0.x = fmaf(va, w.x, a0.x); a0.y = fmaf(va, w.y, a0.y);
                a0.z = fmaf(va, w.z, a0.z); a0.w = fmaf(va, w.w, a0.w);
                a1.x = fmaf(vb, w.x, a1.x); a1.y = fmaf(vb, w.y, a1.y);
                a1.z = fmaf(vb, w.z, a1.z); a1.w = fmaf(vb, w.w, a1.w);
            }
        }
        __stcg((float4*)(wc_l + (i0 + rr)     * D + c4 * 4), a0);
        __stcg((float4*)(wc_l + (i0 + rr + 4) * D + c4 * 4), a1);
    }
    sense ^= 1; grid_barrier(sense);

    // ============ layers ============
    for (int l = 0; l < NL; ++l) {
        // ---- stage A: h2 = h + LN1(h) @ Wcomb + bo ----
        {
            const int b  = blk >> 3;
            const int j0 = (blk & 7) * 32;

            float v = __ldcg(g_h + b * D + tid);
            float s  = blockReduceSum(v, red);
            float sq = blockReduceSum(v * v, red);
            float mu  = s * (1.0f / D);
            float var = sq * (1.0f / D) - mu * mu;
            float inv = rsqrtf(var + 1e-5f);
            buf[tid] = (v - mu) * inv * ln1_s[l * D + tid] + ln1_b[l * D + tid];
            __syncthreads();

            const int c4 = tid & 7;    // 4 cols within 32-col tile
            const int ks = tid >> 3;   // 32 K-slices of 8
            const float* Wc = g_wc + (size_t)l * D * D;
            float4 a = make_float4(0.f,0.f,0.f,0.f);
            #pragma unroll
            for (int i = 0; i < 8; ++i) {
                int k = ks * 8 + i;
                float4 w = __ldcg((const float4*)(Wc + k * D + j0) + c4);
                float yk = buf[k];
                a.x = fmaf(yk, w.x, a.x); a.y = fmaf(yk, w.y, a.y);
                a.z = fmaf(yk, w.z, a.z); a.w = fmaf(yk, w.w, a.w);
            }
            float* ps = buf + 256;               // [col*33 + slice]
            ps[(c4*4+0)*33 + ks] = a.x;
            ps[(c4*4+1)*33 + ks] = a.y;
            ps[(c4*4+2)*33 + ks] = a.z;
            ps[(c4*4+3)*33 + ks] = a.w;
            __syncthreads();
            if (tid < 32) {
                float acc = 0.0f;
                #pragma unroll
                for (int s2 = 0; s2 < 32; ++s2) acc += ps[tid * 33 + s2];
                float hn = __ldcg(g_h + b * D + j0 + tid) + acc + bo[l * D + j0 + tid];
                __stcg(g_h2 + b * D + j0 + tid, hn);
            }
        }
        sense ^= 1; grid_barrier(sense);

        // ---- stage B: g = gelu(LN2(h2) @ w1 + b1) ----
        {
            const int b  = blk >> 3;
            const int j0 = (blk & 7) * 128;

            float v = __ldcg(g_h2 + b * D + tid);
            float s  = blockReduceSum(v, red);
            float sq = blockReduceSum(v * v, red);
            float mu  = s * (1.0f / D);
            float var = sq * (1.0f / D) - mu * mu;
            float inv = rsqrtf(var + 1e-5f);
            buf[tid] = (v - mu) * inv * ln2_s[l * D + tid] + ln2_b[l * D + tid];
            __syncthreads();

            const int c4 = tid & 31;   // 4 cols within 128-col tile
            const int ks = tid >> 5;   // 8 K-slices of 32
            const float* W1 = w1 + (size_t)l * D * F;
            float4 a = make_float4(0.f,0.f,0.f,0.f);
            #pragma unroll 8
            for (int i = 0; i < 32; ++i) {
                int k = ks * 32 + i;
                float4 w = __ldcg((const float4*)(W1 + k * F + j0) + c4);
                float yk = buf[k];
                a.x = fmaf(yk, w.x, a.x); a.y = fmaf(yk, w.y, a.y);
                a.z = fmaf(yk, w.z, a.z); a.w = fmaf(yk, w.w, a.w);
            }
            float* ps = buf + 256;               // [col*9 + slice]
            ps[(c4*4+0)*9 + ks] = a.x;
            ps[(c4*4+1)*9 + ks] = a.y;
            ps[(c4*4+2)*9 + ks] = a.z;
            ps[(c4*4+3)*9 + ks] = a.w;
            __syncthreads();
            if (tid < 128) {
                float acc = b1[l * F + j0 + tid];
                #pragma unroll
                for (int s2 = 0; s2 < 8; ++s2) acc += ps[tid * 9 + s2];
                __stcg(g_g + b * F + j0 + tid, gelu_tanh(acc));
            }
        }
        sense ^= 1; grid_barrier(sense);

        // ---- stage C: h = h2 + g @ w2 + b2 ----
        {
            const int b  = blk >> 3;
            const int j0 = (blk & 7) * 32;

            float4 gv = __ldcg((const float4*)(g_g + b * F) + tid);
            *(float4*)(buf + tid * 4) = gv;      // buf[0..1023] = g
            __syncthreads();

            const int c4 = tid & 7;
            const int ks = tid >> 3;             // 32 K-slices of 32
            const float* W2 = w2 + (size_t)l * F * D;
            float4 a = make_float4(0.f,0.f,0.f,0.f);
            #pragma unroll 8
            for (int i = 0; i < 32; ++i) {
                int k = ks * 32 + i;
                float4 w = __ldcg((const float4*)(W2 + k * D + j0) + c4);
                float yk = buf[k];
                a.x = fmaf(yk, w.x, a.x); a.y = fmaf(yk, w.y, a.y);
                a.z = fmaf(yk, w.z, a.z); a.w = fmaf(yk, w.w, a.w);
            }
            float* ps = buf + 1024;              // [col*33 + slice]
            ps[(c4*4+0)*33 + ks] = a.x;
            ps[(c4*4+1)*33 + ks] = a.y;
            ps[(c4*4+2)*33 + ks] = a.z;
            ps[(c4*4+3)*33 + ks] = a.w;
            __syncthreads();
            if (tid < 32) {
                float acc = b2[l * D + j0 + tid];
                #pragma unroll
                for (int s2 = 0; s2 < 32; ++s2) acc += ps[tid * 33 + s2];
                float hn = __ldcg(g_h2 + b * D + j0 + tid) + acc;
                __stcg(g_h + b * D + j0 + tid, hn);
            }
        }
        sense ^= 1; grid_barrier(sense);
    }

    // ============ classifier ============
    if (blk < B16) {
        const int b = blk;
        buf[tid] = __ldcg(g_h + b * D + tid);
        __syncthreads();
        float* ps = buf + 256;                   // [c*17 + slice]
        if (tid < 160) {
            const int c = tid >> 4;              // 0..9
            const int s = tid & 15;              // 16 K-slices of 16
            float acc = 0.0f;
            #pragma unroll
            for (int i = 0; i < 16; ++i) {
                int k = s * 16 + i;
                acc = fmaf(buf[k], wcls[k * NC + c], acc);
            }
            ps[c * 17 + s] = acc;
        }
        __syncthreads();
        if (tid < NC) {
            float acc = bcls[tid];
            #pragma unroll
            for (int s = 0; s < 16; ++s) acc += ps[tid * 17 + s];
            out[b * NC + tid] = acc;
        }
    }
}

extern "C" void kernel_launch(void* const* d_in, const int* in_sizes, int n_in,
                              void* d_out, int out_size)
{
    const int*   xx      = (const int*)  d_in[0];
    const float* emb_tok = (const float*)d_in[1];
    const float* emb_pos = (const float*)d_in[2];
    const float* ln1_s   = (const float*)d_in[4];
    const float* ln1_b   = (const float*)d_in[5];
    const float* wv      = (const float*)d_in[8];
    const float* wo      = (const float*)d_in[9];
    const float* bo      = (const float*)d_in[10];
    const float* ln2_s   = (const float*)d_in[11];
    const float* ln2_b   = (const float*)d_in[12];
    const float* w1      = (const float*)d_in[13];
    const float* b1      = (const float*)d_in[14];
    const float* w2      = (const float*)d_in[15];
    const float* b2      = (const float*)d_in[16];
    const float* wcls    = (const float*)d_in[17];
    const float* bcls    = (const float*)d_in[18];
    float* out = (float*)d_out;

    const int B = out_size / NC;      // 16
    const int N = in_sizes[0] / B;    // 4096

    performer_cls_kernel<<<GRID, TPB>>>(xx, emb_tok, emb_pos, ln1_s, ln1_b,
                                        wv, wo, bo, ln2_s, ln2_b,
                                        w1, b1, w2, b2, wcls, bcls, out, N);
}

// round 5
// speedup vs baseline: 2.2065x; 2.2065x over previous
#include <cuda_runtime.h>
#include <cuda_bf16.h>
#include <cooperative_groups.h>

namespace cg = cooperative_groups;

#define D    256
#define F    1024
#define NL   4
#define NC   10
#define CS   8      // cluster size (ranks per batch element)
#define TPB  256

// two-value block reduction (sum, sumsq) over 256 threads
__device__ __forceinline__ float2 blockReduceSum2(float a, float b, float2* red2) {
    #pragma unroll
    for (int o = 16; o > 0; o >>= 1) {
        a += __shfl_xor_sync(0xffffffffu, a, o);
        b += __shfl_xor_sync(0xffffffffu, b, o);
    }
    int wid = threadIdx.x >> 5;
    if ((threadIdx.x & 31) == 0) red2[wid] = make_float2(a, b);
    __syncthreads();
    if (threadIdx.x < 8) {
        float2 t = red2[threadIdx.x];
        #pragma unroll
        for (int o = 4; o > 0; o >>= 1) {
            t.x += __shfl_xor_sync(0xffu, t.x, o);
            t.y += __shfl_xor_sync(0xffu, t.y, o);
        }
        if (threadIdx.x == 0) red2[0] = t;
    }
    __syncthreads();
    float2 r = red2[0];
    __syncthreads();
    return r;
}

__device__ __forceinline__ float gelu_tanh(float x) {
    const float c = 0.7978845608028654f;   // sqrt(2/pi)
    float u = c * (x + 0.044715f * x * x * x);
    return 0.5f * x * (1.0f + tanhf(u));
}

__global__ void __launch_bounds__(TPB, 1) __cluster_dims__(CS, 1, 1)
performer_cls_kernel(const int*   __restrict__ xx,
                     const float* __restrict__ emb_tok,
                     const float* __restrict__ emb_pos,
                     const float* __restrict__ ln1_s,
                     const float* __restrict__ ln1_b,
                     const float* __restrict__ wv,
                     const float* __restrict__ wo,
                     const float* __restrict__ bo,
                     const float* __restrict__ ln2_s,
                     const float* __restrict__ ln2_b,
                     const float* __restrict__ w1,
                     const float* __restrict__ b1,
                     const float* __restrict__ w2,
                     const float* __restrict__ b2,
                     const float* __restrict__ wcls,
                     const float* __restrict__ bcls,
                     float* __restrict__ out,
                     int N)
{
    __shared__ float  sh_h[D];       // residual stream (replicated per rank)
    __shared__ float  sh_y[D];       // LN output (locally computed, identical)
    __shared__ float  sh_g[F];       // v0 (first 256) / MLP hidden (full)
    __shared__ float  sh_c[128];     // my output chunk staging
    __shared__ float  ps[128 * 9];   // split-K partials (1152 >= 32*33)
    __shared__ float2 red2[8];

    cg::cluster_group cluster = cg::this_cluster();
    const int tid = threadIdx.x;
    const int r   = (int)cluster.block_rank();       // 0..7
    const int b   = blockIdx.x >> 3;                 // batch element

    const int p_dst  = tid >> 5;                     // peer rank for broadcast
    const int p_lane = tid & 31;

    // ---- init: every rank computes full h0 locally (no comm) ----
    {
        const int tok = xx[b * N];
        sh_h[tid] = emb_tok[tok * D + tid] + emb_pos[tid];
    }
    __syncthreads();

    for (int l = 0; l < NL; ++l) {
        // ======== stage A1: sh_g[0..255] = LN1(h) @ wv (chunked) ========
        {
            float v = sh_h[tid];
            float2 ss = blockReduceSum2(v, v * v, red2);
            float mu  = ss.x * (1.0f / D);
            float var = ss.y * (1.0f / D) - mu * mu;
            float inv = rsqrtf(var + 1e-5f);
            sh_y[tid] = (v - mu) * inv * ln1_s[l * D + tid] + ln1_b[l * D + tid];
            __syncthreads();

            const int j0 = r * 32;
            const int c4 = tid & 7;          // 4 cols each
            const int ks = tid >> 3;         // 32 K-slices of 8
            const float* W = wv + (size_t)l * D * D;
            float4 a = make_float4(0.f, 0.f, 0.f, 0.f);
            #pragma unroll
            for (int i = 0; i < 8; ++i) {
                int k = ks * 8 + i;
                float4 w = *((const float4*)(W + (size_t)k * D + j0) + c4);
                float yk = sh_y[k];
                a.x = fmaf(yk, w.x, a.x); a.y = fmaf(yk, w.y, a.y);
                a.z = fmaf(yk, w.z, a.z); a.w = fmaf(yk, w.w, a.w);
            }
            ps[(c4 * 4 + 0) * 33 + ks] = a.x;
            ps[(c4 * 4 + 1) * 33 + ks] = a.y;
            ps[(c4 * 4 + 2) * 33 + ks] = a.z;
            ps[(c4 * 4 + 3) * 33 + ks] = a.w;
            __syncthreads();
            if (tid < 32) {
                float acc = 0.0f;
                #pragma unroll
                for (int s = 0; s < 32; ++s) acc += ps[tid * 33 + s];
                sh_c[tid] = acc;
            }
            __syncthreads();
            // broadcast my 32-float v0 chunk to all 8 ranks' sh_g[r*32 ..]
            float* dst = cluster.map_shared_rank(sh_g, p_dst);
            dst[r * 32 + p_lane] = sh_c[p_lane];
        }
        cluster.sync();

        // ======== stage A2: h = h + v0 @ wo + bo (chunked) ========
        {
            const int j0 = r * 32;
            const int c4 = tid & 7;
            const int ks = tid >> 3;
            const float* W = wo + (size_t)l * D * D;
            float4 a = make_float4(0.f, 0.f, 0.f, 0.f);
            #pragma unroll
            for (int i = 0; i < 8; ++i) {
                int k = ks * 8 + i;
                float4 w = *((const float4*)(W + (size_t)k * D + j0) + c4);
                float yk = sh_g[k];          // v0
                a.x = fmaf(yk, w.x, a.x); a.y = fmaf(yk, w.y, a.y);
                a.z = fmaf(yk, w.z, a.z); a.w = fmaf(yk, w.w, a.w);
            }
            ps[(c4 * 4 + 0) * 33 + ks] = a.x;
            ps[(c4 * 4 + 1) * 33 + ks] = a.y;
            ps[(c4 * 4 + 2) * 33 + ks] = a.z;
            ps[(c4 * 4 + 3) * 33 + ks] = a.w;
            __syncthreads();
            if (tid < 32) {
                float acc = bo[l * D + r * 32 + tid];
                #pragma unroll
                for (int s = 0; s < 32; ++s) acc += ps[tid * 33 + s];
                sh_c[tid] = sh_h[r * 32 + tid] + acc;   // new h chunk
            }
            __syncthreads();
            float* dst = cluster.map_shared_rank(sh_h, p_dst);
            dst[r * 32 + p_lane] = sh_c[p_lane];
        }
        cluster.sync();

        // ======== stage B: hidden = gelu(LN2(h) @ w1 + b1) (chunked) ========
        {
            float v = sh_h[tid];
            float2 ss = blockReduceSum2(v, v * v, red2);
            float mu  = ss.x * (1.0f / D);
            float var = ss.y * (1.0f / D) - mu * mu;
            float inv = rsqrtf(var + 1e-5f);
            sh_y[tid] = (v - mu) * inv * ln2_s[l * D + tid] + ln2_b[l * D + tid];
            __syncthreads();

            const int j0 = r * 128;
            const int c4 = tid & 31;         // 4 cols each -> 128 cols
            const int ks = tid >> 5;         // 8 K-slices of 32
            const float* W1 = w1 + (size_t)l * D * F;
            float4 a = make_float4(0.f, 0.f, 0.f, 0.f);
            #pragma unroll
            for (int i = 0; i < 32; ++i) {
                int k = ks * 32 + i;
                float4 w = *((const float4*)(W1 + (size_t)k * F + j0) + c4);
                float yk = sh_y[k];
                a.x = fmaf(yk, w.x, a.x); a.y = fmaf(yk, w.y, a.y);
                a.z = fmaf(yk, w.z, a.z); a.w = fmaf(yk, w.w, a.w);
            }
            ps[(c4 * 4 + 0) * 9 + ks] = a.x;
            ps[(c4 * 4 + 1) * 9 + ks] = a.y;
            ps[(c4 * 4 + 2) * 9 + ks] = a.z;
            ps[(c4 * 4 + 3) * 9 + ks] = a.w;
            __syncthreads();
            if (tid < 128) {
                float acc = b1[l * F + j0 + tid];
                #pragma unroll
                for (int s = 0; s < 8; ++s) acc += ps[tid * 9 + s];
                sh_c[tid] = gelu_tanh(acc);
            }
            __syncthreads();
            float* dst = cluster.map_shared_rank(sh_g, p_dst);
            #pragma unroll
            for (int e = 0; e < 4; ++e)
                dst[r * 128 + p_lane + e * 32] = sh_c[p_lane + e * 32];
        }
        cluster.sync();

        // ======== stage C: h = h + hidden @ w2 + b2 (chunked) ========
        {
            const int j0 = r * 32;
            const int c4 = tid & 7;
            const int ks = tid >> 3;         // 32 K-slices of 32
            const float* W2 = w2 + (size_t)l * F * D;
            float4 a = make_float4(0.f, 0.f, 0.f, 0.f);
            #pragma unroll
            for (int i = 0; i < 32; ++i) {
                int k = ks * 32 + i;
                float4 w = *((const float4*)(W2 + (size_t)k * D + j0) + c4);
                float yk = sh_g[k];          // hidden
                a.x = fmaf(yk, w.x, a.x); a.y = fmaf(yk, w.y, a.y);
                a.z = fmaf(yk, w.z, a.z); a.w = fmaf(yk, w.w, a.w);
            }
            ps[(c4 * 4 + 0) * 33 + ks] = a.x;
            ps[(c4 * 4 + 1) * 33 + ks] = a.y;
            ps[(c4 * 4 + 2) * 33 + ks] = a.z;
            ps[(c4 * 4 + 3) * 33 + ks] = a.w;
            __syncthreads();
            if (tid < 32) {
                float acc = b2[l * D + r * 32 + tid];
                #pragma unroll
                for (int s = 0; s < 32; ++s) acc += ps[tid * 33 + s];
                sh_c[tid] = sh_h[r * 32 + tid] + acc;
            }
            __syncthreads();
            float* dst = cluster.map_shared_rank(sh_h, p_dst);
            dst[r * 32 + p_lane] = sh_c[p_lane];
        }
        cluster.sync();
    }

    // ======== classifier (rank 0 of each cluster) ========
    if (r == 0) {
        if (tid < 160) {
            const int c = tid >> 4;          // class 0..9
            const int s = tid & 15;          // 16 K-slices of 16
            float acc = 0.0f;
            #pragma unroll
            for (int i = 0; i < 16; ++i) {
                int k = s * 16 + i;
                acc = fmaf(sh_h[k], wcls[k * NC + c], acc);
            }
            ps[c * 17 + s] = acc;
        }
        __syncthreads();
        if (tid < NC) {
            float acc = bcls[tid];
            #pragma unroll
            for (int s = 0; s < 16; ++s) acc += ps[tid * 17 + s];
            out[b * NC + tid] = acc;
        }
    }
}

extern "C" void kernel_launch(void* const* d_in, const int* in_sizes, int n_in,
                              void* d_out, int out_size)
{
    const int*   xx      = (const int*)  d_in[0];
    const float* emb_tok = (const float*)d_in[1];
    const float* emb_pos = (const float*)d_in[2];
    const float* ln1_s   = (const float*)d_in[4];
    const float* ln1_b   = (const float*)d_in[5];
    const float* wv      = (const float*)d_in[8];
    const float* wo      = (const float*)d_in[9];
    const float* bo      = (const float*)d_in[10];
    const float* ln2_s   = (const float*)d_in[11];
    const float* ln2_b   = (const float*)d_in[12];
    const float* w1      = (const float*)d_in[13];
    const float* b1      = (const float*)d_in[14];
    const float* w2      = (const float*)d_in[15];
    const float* b2      = (const float*)d_in[16];
    const float* wcls    = (const float*)d_in[17];
    const float* bcls    = (const float*)d_in[18];
    float* out = (float*)d_out;

    const int B = out_size / NC;      // 16
    const int N = in_sizes[0] / B;    // 4096

    performer_cls_kernel<<<B * CS, TPB>>>(xx, emb_tok, emb_pos, ln1_s, ln1_b,
                                          wv, wo, bo, ln2_s, ln2_b,
                                          w1, b1, w2, b2, wcls, bcls, out, N);
}